// round 4
// baseline (speedup 1.0000x reference)
#include <cuda_runtime.h>

// LogicConv3d: B=16, C=3, H=W=32, K=64, P=784, S=64, 7-level soft logic tree.
// d_in: [0]=x f32[16,3,32,32], [1..7]=w0..w6 f32[2^(6-l),64,16],
//       [8]=left_idx i32[64,784,64,3], [9]=right_idx i32[64,784,64,3]
// d_out: f32[16,64,784,1]

#define B_ 16
#define C_ 3
#define HW_ 1024
#define CHW_ 3072
#define K_ 64
#define P_ 784
#define KP_ (K_ * P_)     // 50176
#define NROWS 127
#define TP 16             // patches per block (784 = 49*16)

// scratch
__device__ float4 g_coef[K_ * NROWS];     // per-(k,node) gate coeffs
__device__ float  g_xt[CHW_ * B_];        // x transposed: [offset][batch] (192KB)

__constant__ float G4[16][4] = {
    {0,0,0,0},{0,0,0,1},{0,1,0,-1},{0,1,0,0},
    {0,0,1,-1},{0,0,1,0},{0,1,1,-2},{0,1,1,-1},
    {1,-1,-1,1},{1,-1,-1,2},{1,0,-1,0},{1,0,-1,1},
    {1,-1,0,0},{1,-1,0,1},{1,0,0,-1},{1,0,0,0}};

// ---------------------------------------------------------------------------
// Prep (tiny): softmax coeffs + x transpose.
// ---------------------------------------------------------------------------
__global__ void prep_kernel(const float* __restrict__ x,
                            const float* __restrict__ w0, const float* __restrict__ w1,
                            const float* __restrict__ w2, const float* __restrict__ w3,
                            const float* __restrict__ w4, const float* __restrict__ w5,
                            const float* __restrict__ w6) {
    int r = blockIdx.x * 256 + threadIdx.x;
    if (r < NROWS * K_) {
        int row = r >> 6;
        int k   = r & 63;
        int bse = 0, n = 64, l = 0;
        while (row >= bse + n) { bse += n; n >>= 1; ++l; }
        int s = row - bse;
        const float* ws[7] = {w0, w1, w2, w3, w4, w5, w6};
        const float* p = ws[l] + (s * K_ + k) * 16;
        float v[16], m = -1e30f;
#pragma unroll
        for (int i = 0; i < 16; ++i) { v[i] = p[i]; m = fmaxf(m, v[i]); }
        float sum = 0.f, c0 = 0.f, c1 = 0.f, c2 = 0.f, c3 = 0.f;
#pragma unroll
        for (int i = 0; i < 16; ++i) {
            float e = expf(v[i] - m);
            sum += e;
            c0 += e * G4[i][0]; c1 += e * G4[i][1];
            c2 += e * G4[i][2]; c3 += e * G4[i][3];
        }
        float inv = 1.f / sum;
        g_coef[k * NROWS + row] = make_float4(c0 * inv, c1 * inv, c2 * inv, c3 * inv);
        return;
    }
    r -= NROWS * K_;
    if (r < CHW_ * B_) {
        int b = r & 15, off = r >> 4;
        g_xt[r] = x[b * CHW_ + off];
    }
}

// ---------------------------------------------------------------------------
// Main kernel: 64 threads = 4 batch-groups (float4) x 16 patches, one k.
// idx loads use streaming hint (__ldcs) so they don't evict xt from L1.
// SMEM offsets are pre-scaled to BYTE offsets (x64) -> 1 IADD per gather.
// Depth-2 software pipeline keeps 4 gathers in flight every iteration.
// ---------------------------------------------------------------------------
__device__ __forceinline__ float4 gate4(float4 a, float4 b, float4 c) {
    float4 r;
    r.x = fmaf(b.x, fmaf(c.w, a.x, c.z), fmaf(c.y, a.x, c.x));
    r.y = fmaf(b.y, fmaf(c.w, a.y, c.z), fmaf(c.y, a.y, c.x));
    r.z = fmaf(b.z, fmaf(c.w, a.z, c.z), fmaf(c.y, a.z, c.x));
    r.w = fmaf(b.w, fmaf(c.w, a.w, c.z), fmaf(c.y, a.w, c.x));
    return r;
}

__global__ __launch_bounds__(64)
void logic_kernel(const int* __restrict__ lidx,
                  const int* __restrict__ ridx,
                  float* __restrict__ out) {
    __shared__ int    soff[TP][132];   // [patch][2*s+(l/r)] BYTE offsets, pad->bank-free
    __shared__ float4 scoef[NROWS];

    const int k   = blockIdx.y;
    const int p0  = blockIdx.x * TP;
    const int tid = threadIdx.x;

    for (int i = tid; i < NROWS; i += 64) scoef[i] = g_coef[k * NROWS + i];

    // decode idx triples -> byte offsets (streaming loads: don't pollute L1)
    {
        const int* lb = lidx + (k * P_ + p0) * (64 * 3);
        const int* rb = ridx + (k * P_ + p0) * (64 * 3);
#pragma unroll
        for (int e = tid; e < TP * 64; e += 64) {
            int pl = e >> 6, s = e & 63;
            int h = __ldcs(lb + 3 * e), w = __ldcs(lb + 3 * e + 1), c = __ldcs(lb + 3 * e + 2);
            soff[pl][2 * s]     = (c * HW_ + h * 32 + w) * 64;
            h = __ldcs(rb + 3 * e); w = __ldcs(rb + 3 * e + 1); c = __ldcs(rb + 3 * e + 2);
            soff[pl][2 * s + 1] = (c * HW_ + h * 32 + w) * 64;
        }
    }
    __syncthreads();

    const int bg = tid & 3;            // batch group (4 floats)
    const int pl = tid >> 2;           // patch lane 0..15
    const char* xtb = (const char*)g_xt + bg * 16;

    float4 st[7];
    int sp = 0;

    // pipeline prologue: iteration 0's loads
    int2   o  = *(const int2*)&soff[pl][0];
    float4 A  = *(const float4*)(xtb + o.x);
    float4 Bv = *(const float4*)(xtb + o.y);

#pragma unroll
    for (int s = 0; s < 64; ++s) {
        int2 o2; float4 A2, B2;
        if (s < 63) {                          // prefetch next iteration
            o2 = *(const int2*)&soff[pl][2 * (s + 1)];
            A2 = *(const float4*)(xtb + o2.x);
            B2 = *(const float4*)(xtb + o2.y);
        }
        float4 v = gate4(A, Bv, scoef[s]);
#pragma unroll
        for (int l = 1; l <= 6; ++l) {
            if (((s + 1) & ((1 << l) - 1)) == 0) {
                v = gate4(st[--sp], v, scoef[(128 - (128 >> l)) + (s >> l)]);
            }
        }
        st[sp++] = v;
        A = A2; Bv = B2; o = o2;
    }

    float4 r = st[0];
    long ob0 = (long)(bg * 4) * KP_ + k * P_ + p0 + pl;
    out[ob0]           = r.x;
    out[ob0 + KP_]     = r.y;
    out[ob0 + 2 * KP_] = r.z;
    out[ob0 + 3 * KP_] = r.w;
}

// ---------------------------------------------------------------------------
extern "C" void kernel_launch(void* const* d_in, const int* in_sizes, int n_in,
                              void* d_out, int out_size) {
    const float* x  = (const float*)d_in[0];
    const float* w0 = (const float*)d_in[1];
    const float* w1 = (const float*)d_in[2];
    const float* w2 = (const float*)d_in[3];
    const float* w3 = (const float*)d_in[4];
    const float* w4 = (const float*)d_in[5];
    const float* w5 = (const float*)d_in[6];
    const float* w6 = (const float*)d_in[7];
    const int* lidx = (const int*)d_in[8];
    const int* ridx = (const int*)d_in[9];
    float* out = (float*)d_out;

    int prep_work = NROWS * K_ + CHW_ * B_;           // 57280
    prep_kernel<<<(prep_work + 255) / 256, 256>>>(x, w0, w1, w2, w3, w4, w5, w6);
    logic_kernel<<<dim3(P_ / TP, K_), 64>>>(lidx, ridx, out);
}

// round 5
// speedup vs baseline: 1.0299x; 1.0299x over previous
#include <cuda_runtime.h>

// LogicConv3d: B=16, C=3, H=W=32, K=64, P=784, S=64, 7-level soft logic tree.
// d_in: [0]=x f32[16,3,32,32], [1..7]=w0..w6 f32[2^(6-l),64,16],
//       [8]=left_idx i32[64,784,64,3], [9]=right_idx i32[64,784,64,3]
// d_out: f32[16,64,784,1]

#define B_ 16
#define C_ 3
#define HW_ 1024
#define CHW_ 3072
#define K_ 64
#define P_ 784
#define KP_ (K_ * P_)     // 50176
#define NROWS 127
#define TP 16             // patches per block (784 = 49*16)

// scratch
__device__ float4 g_coef[K_ * NROWS];     // per-(k,node) gate coeffs
__device__ float  g_xt[CHW_ * B_];        // x transposed: [offset][batch] (192KB)

__constant__ float G4[16][4] = {
    {0,0,0,0},{0,0,0,1},{0,1,0,-1},{0,1,0,0},
    {0,0,1,-1},{0,0,1,0},{0,1,1,-2},{0,1,1,-1},
    {1,-1,-1,1},{1,-1,-1,2},{1,0,-1,0},{1,0,-1,1},
    {1,-1,0,0},{1,-1,0,1},{1,0,0,-1},{1,0,0,0}};

// ---------------------------------------------------------------------------
// Prep (tiny): softmax coeffs + x transpose.
// ---------------------------------------------------------------------------
__global__ void prep_kernel(const float* __restrict__ x,
                            const float* __restrict__ w0, const float* __restrict__ w1,
                            const float* __restrict__ w2, const float* __restrict__ w3,
                            const float* __restrict__ w4, const float* __restrict__ w5,
                            const float* __restrict__ w6) {
    int r = blockIdx.x * 256 + threadIdx.x;
    if (r < NROWS * K_) {
        int row = r >> 6;
        int k   = r & 63;
        int bse = 0, n = 64, l = 0;
        while (row >= bse + n) { bse += n; n >>= 1; ++l; }
        int s = row - bse;
        const float* ws[7] = {w0, w1, w2, w3, w4, w5, w6};
        const float* p = ws[l] + (s * K_ + k) * 16;
        float v[16], m = -1e30f;
#pragma unroll
        for (int i = 0; i < 16; ++i) { v[i] = p[i]; m = fmaxf(m, v[i]); }
        float sum = 0.f, c0 = 0.f, c1 = 0.f, c2 = 0.f, c3 = 0.f;
#pragma unroll
        for (int i = 0; i < 16; ++i) {
            float e = expf(v[i] - m);
            sum += e;
            c0 += e * G4[i][0]; c1 += e * G4[i][1];
            c2 += e * G4[i][2]; c3 += e * G4[i][3];
        }
        float inv = 1.f / sum;
        g_coef[k * NROWS + row] = make_float4(c0 * inv, c1 * inv, c2 * inv, c3 * inv);
        return;
    }
    r -= NROWS * K_;
    if (r < CHW_ * B_) {
        int b = r & 15, off = r >> 4;
        g_xt[r] = x[b * CHW_ + off];
    }
}

// ---------------------------------------------------------------------------
// Main kernel: 128 threads = 8 batch-pairs (float2) x 16 patches, one k.
// Thin threads (float2) double warp count at the same L1 wavefront cost,
// and halve the register stack -> ~75% occupancy -> ~1.6x more gathers
// in flight. Offsets stored as ushort2 element indices in SMEM.
// ---------------------------------------------------------------------------
__device__ __forceinline__ float2 gate2(float2 a, float2 b, float4 c) {
    float2 r;
    r.x = fmaf(b.x, fmaf(c.w, a.x, c.z), fmaf(c.y, a.x, c.x));
    r.y = fmaf(b.y, fmaf(c.w, a.y, c.z), fmaf(c.y, a.y, c.x));
    return r;
}

__global__ __launch_bounds__(128, 12)
void logic_kernel(const int* __restrict__ lidx,
                  const int* __restrict__ ridx,
                  float* __restrict__ out) {
    __shared__ ushort2 soff[TP][66];   // [patch][s] = (left,right) element offsets
    __shared__ float4  scoef[NROWS];

    const int k   = blockIdx.y;
    const int p0  = blockIdx.x * TP;
    const int tid = threadIdx.x;

    if (tid < NROWS) scoef[tid] = g_coef[k * NROWS + tid];

    // decode idx triples -> element offsets (coalesced reads, shared by all b)
    {
        const int* lb = lidx + (k * P_ + p0) * (64 * 3);
        const int* rb = ridx + (k * P_ + p0) * (64 * 3);
#pragma unroll
        for (int e = tid; e < TP * 64; e += 128) {
            int pl = e >> 6, s = e & 63;
            int h = lb[3 * e], w = lb[3 * e + 1], c = lb[3 * e + 2];
            int lo = c * HW_ + h * 32 + w;
            h = rb[3 * e]; w = rb[3 * e + 1]; c = rb[3 * e + 2];
            int ro = c * HW_ + h * 32 + w;
            soff[pl][s] = make_ushort2((unsigned short)lo, (unsigned short)ro);
        }
    }
    __syncthreads();

    const int bg2 = tid & 7;           // batch pair (2 floats)
    const int pl  = tid >> 3;          // patch lane 0..15
    const char* xtb = (const char*)g_xt + bg2 * 8;

    float2 st[7];
    int sp = 0;
#pragma unroll
    for (int s = 0; s < 64; ++s) {
        ushort2 o = soff[pl][s];
        float2 A  = *(const float2*)(xtb + ((int)o.x << 6));
        float2 Bv = *(const float2*)(xtb + ((int)o.y << 6));
        float2 v = gate2(A, Bv, scoef[s]);
#pragma unroll
        for (int l = 1; l <= 6; ++l) {
            if (((s + 1) & ((1 << l) - 1)) == 0) {
                v = gate2(st[--sp], v, scoef[(128 - (128 >> l)) + (s >> l)]);
            }
        }
        st[sp++] = v;
    }

    float2 r = st[0];
    long ob0 = (long)(bg2 * 2) * KP_ + k * P_ + p0 + pl;
    out[ob0]       = r.x;
    out[ob0 + KP_] = r.y;
}

// ---------------------------------------------------------------------------
extern "C" void kernel_launch(void* const* d_in, const int* in_sizes, int n_in,
                              void* d_out, int out_size) {
    const float* x  = (const float*)d_in[0];
    const float* w0 = (const float*)d_in[1];
    const float* w1 = (const float*)d_in[2];
    const float* w2 = (const float*)d_in[3];
    const float* w3 = (const float*)d_in[4];
    const float* w4 = (const float*)d_in[5];
    const float* w5 = (const float*)d_in[6];
    const float* w6 = (const float*)d_in[7];
    const int* lidx = (const int*)d_in[8];
    const int* ridx = (const int*)d_in[9];
    float* out = (float*)d_out;

    int prep_work = NROWS * K_ + CHW_ * B_;           // 57280
    prep_kernel<<<(prep_work + 255) / 256, 256>>>(x, w0, w1, w2, w3, w4, w5, w6);
    logic_kernel<<<dim3(P_ / TP, K_), 128>>>(lidx, ridx, out);
}